// round 1
// baseline (speedup 1.0000x reference)
#include <cuda_runtime.h>

#define NT   10
#define DIMX 240
#define NSC  64
#define NF   112
#define EPSV 1e-5f

// scratch layout: [sum2: NT*DIMX][sum1: NT*NSC][cnt: NT]
#define SCR_SUM1 (NT*DIMX)
#define SCR_CNT  (NT*DIMX + NT*NSC)
#define SCR_SIZE (NT*DIMX + NT*NSC + NT)

__device__ float g_scr[SCR_SIZE];
__device__ __align__(16) float g_A[NT*DIMX];
__device__ __align__(16) float g_B[NT*DIMX];

// ---------------------------------------------------------------- zero scratch
__global__ void k_zero() {
    int i = blockIdx.x * blockDim.x + threadIdx.x;
    if (i < SCR_SIZE) g_scr[i] = 0.0f;
}

// ---------------------------------------------------------------- stats pass
// blockDim = 240. Thread `tid` exclusively owns element column `tid` of the
// per-type shared accumulators -> plain (atomic-free) shared RMW.
__global__ __launch_bounds__(DIMX) void k_stats(const float* __restrict__ x,
                                                const int* __restrict__ ty,
                                                int batch) {
    __shared__ float s2[NT][DIMX];   // sum of x^2 per element
    __shared__ float s1[NT][NSC];    // sum of x for scalar elements
    __shared__ float scnt[NT];

    const int tid = threadIdx.x;
#pragma unroll
    for (int t = 0; t < NT; t++) {
        s2[t][tid] = 0.0f;
        if (tid < NSC) s1[t][tid] = 0.0f;
    }
    if (tid < NT) scnt[tid] = 0.0f;
    __syncthreads();

    const int U = 8;
    const int stride = gridDim.x * U;
    for (int base = blockIdx.x * U; base < batch; base += stride) {
        float v[U];
        int   t[U];
        // front-batch the loads for MLP
#pragma unroll
        for (int i = 0; i < U; i++) {
            int r = base + i;
            if (r < batch) {
                v[i] = x[r * DIMX + tid];
                t[i] = ty[r];
            }
        }
#pragma unroll
        for (int i = 0; i < U; i++) {
            int r = base + i;
            if (r < batch) {
                int tt = t[i];
                float vi = v[i];
                s2[tt][tid] += vi * vi;           // exclusive column -> no atomic
                if (tid < NSC) s1[tt][tid] += vi;
                if (tid == 0)  scnt[tt] += 1.0f;
            }
        }
    }
    __syncthreads();

#pragma unroll
    for (int t = 0; t < NT; t++) {
        atomicAdd(&g_scr[t * DIMX + tid], s2[t][tid]);
        if (tid < NSC) atomicAdd(&g_scr[SCR_SUM1 + t * NSC + tid], s1[t][tid]);
    }
    if (tid < NT) atomicAdd(&g_scr[SCR_CNT + tid], scnt[tid]);
}

// ---------------------------------------------------------------- table build
// One block of 240 threads; builds A[t][e], B[t][e] so that
//   out[b,e] = x[b,e] * A[ty[b]][e] + B[ty[b]][e]
__global__ __launch_bounds__(DIMX) void k_tables(const float* __restrict__ w,
                                                 const float* __restrict__ b) {
    const int e = threadIdx.x;
    for (int t = 0; t < NT; t++) {
        float cnt = fmaxf(g_scr[SCR_CNT + t], 1.0f);
        float inv = 1.0f / cnt;
        float A, Bv;
        if (e < NSC) {
            // scalar irrep: center by type-mean, normalize by variance
            float S2   = g_scr[t * DIMX + e];
            float S1   = g_scr[SCR_SUM1 + t * NSC + e];
            float mean = S1 * inv;
            float var  = S2 * inv - mean * mean;
            float s    = rsqrtf(var + EPSV) * w[t * NF + e];
            A  = s;
            Bv = b[t * NSC + e] - mean * s;
        } else if (e < 64 + 32 * 3) {
            // 32x1o
            int m    = (e - 64) / 3;
            int base = 64 + m * 3;
            float S2 = g_scr[t * DIMX + base] + g_scr[t * DIMX + base + 1] +
                       g_scr[t * DIMX + base + 2];
            float fn = S2 * inv * (1.0f / 3.0f);
            A  = rsqrtf(fn + EPSV) * w[t * NF + 64 + m];
            Bv = 0.0f;
        } else {
            // 16x2e
            int m    = (e - 160) / 5;
            int base = 160 + m * 5;
            float S2 = 0.0f;
#pragma unroll
            for (int j = 0; j < 5; j++) S2 += g_scr[t * DIMX + base + j];
            float fn = S2 * inv * 0.2f;
            A  = rsqrtf(fn + EPSV) * w[t * NF + 96 + m];
            Bv = 0.0f;
        }
        g_A[t * DIMX + e] = A;
        g_B[t * DIMX + e] = Bv;
    }
}

// ---------------------------------------------------------------- apply pass
// One float4 per thread; tables (19.2 KB) stay hot in L1/L2.
__global__ __launch_bounds__(256) void k_apply(const float4* __restrict__ x4,
                                               const int* __restrict__ ty,
                                               float4* __restrict__ o4,
                                               int n4) {
    int i = blockIdx.x * blockDim.x + threadIdx.x;
    if (i >= n4) return;
    int row = i / 60;           // DIMX/4 = 60 float4 per row
    int q   = i - row * 60;
    int t   = __ldg(ty + row);
    float4 xv = __ldg(x4 + i);
    const float4* A4 = reinterpret_cast<const float4*>(g_A) + t * 60 + q;
    const float4* B4 = reinterpret_cast<const float4*>(g_B) + t * 60 + q;
    float4 a  = *A4;
    float4 bb = *B4;
    float4 o;
    o.x = fmaf(xv.x, a.x, bb.x);
    o.y = fmaf(xv.y, a.y, bb.y);
    o.z = fmaf(xv.z, a.z, bb.z);
    o.w = fmaf(xv.w, a.w, bb.w);
    o4[i] = o;
}

// ---------------------------------------------------------------- launch
extern "C" void kernel_launch(void* const* d_in, const int* in_sizes, int n_in,
                              void* d_out, int out_size) {
    const float* x  = (const float*)d_in[0];
    const int*   ty = (const int*)d_in[1];
    const float* w  = (const float*)d_in[2];
    const float* b  = (const float*)d_in[3];

    int batch = in_sizes[0] / DIMX;

    k_zero<<<(SCR_SIZE + 255) / 256, 256>>>();
    k_stats<<<592, DIMX>>>(x, ty, batch);
    k_tables<<<1, DIMX>>>(w, b);

    int n4 = batch * (DIMX / 4);
    k_apply<<<(n4 + 255) / 256, 256>>>((const float4*)x, ty, (float4*)d_out, n4);
}

// round 4
// speedup vs baseline: 1.1474x; 1.1474x over previous
#include <cuda_runtime.h>

#define NT   10
#define DIMX 240
#define NSC  64
#define NF   112
#define EPSV 1e-5f
#define RS   4           // replicated accumulator copies (row-subgroups)

// scratch layout: [sum2: NT*DIMX][sum1: NT*NSC][cnt: NT]
#define SCR_SUM1 (NT*DIMX)
#define SCR_CNT  (NT*DIMX + NT*NSC)
#define SCR_SIZE (NT*DIMX + NT*NSC + NT)

__device__ float g_scr[SCR_SIZE];
__device__ __align__(16) float g_A[NT*DIMX];
__device__ __align__(16) float g_B[NT*DIMX];

// ---------------------------------------------------------------- zero scratch
__global__ void k_zero() {
    int i = blockIdx.x * blockDim.x + threadIdx.x;
    if (i < SCR_SIZE) g_scr[i] = 0.0f;
}

// ---------------------------------------------------------------- stats pass
// blockDim = 256. Threads 0..239 active in the main loop.
//   rs  = tid/60  : which accumulator copy / row-subgroup (0..3)
//   c4  = tid%60  : which float4 column group (0..59)
// Each CTA iteration consumes 8 rows (two groups of 4, loads front-batched).
// Exclusive (rs, column) ownership -> plain vectorized smem RMW, no atomics.
__global__ __launch_bounds__(256) void k_stats(const float* __restrict__ x,
                                               const int* __restrict__ ty,
                                               int batch) {
    __shared__ __align__(16) float s2[RS * NT * DIMX];   // x^2 sums
    __shared__ __align__(16) float s1[RS * NT * NSC];    // x sums (scalars)
    __shared__ float scnt[RS * NT];

    const int tid = threadIdx.x;
    for (int i = tid; i < RS * NT * DIMX; i += 256) s2[i] = 0.0f;
    for (int i = tid; i < RS * NT * NSC;  i += 256) s1[i] = 0.0f;
    if (tid < RS * NT) scnt[tid] = 0.0f;
    __syncthreads();

    const int  rs  = tid / 60;
    const int  c4  = tid - rs * 60;
    const int  c   = c4 * 4;
    const bool act = (tid < 240);

    float* const s2base = s2 + rs * (NT * DIMX);
    float* const s1base = s1 + rs * (NT * NSC);

    const int step = gridDim.x * 8;
    for (int base = blockIdx.x * 8; base < batch; base += step) {
        if (act) {
            const int r0 = base + rs;
            const int r1 = base + 4 + rs;
            const bool g0 = (r0 < batch);
            const bool g1 = (r1 < batch);
            float4 v0, v1;
            int t0 = 0, t1 = 0;
            if (g0) { v0 = *(const float4*)(x + (size_t)r0 * DIMX + c); t0 = ty[r0]; }
            if (g1) { v1 = *(const float4*)(x + (size_t)r1 * DIMX + c); t1 = ty[r1]; }
            if (g0) {
                float* a = s2base + t0 * DIMX + c;
                a[0] += v0.x * v0.x; a[1] += v0.y * v0.y;
                a[2] += v0.z * v0.z; a[3] += v0.w * v0.w;
                if (c4 < 16) {
                    float* b = s1base + t0 * NSC + c;
                    b[0] += v0.x; b[1] += v0.y; b[2] += v0.z; b[3] += v0.w;
                }
                if (c4 == 0) scnt[rs * NT + t0] += 1.0f;
            }
            if (g1) {
                float* a = s2base + t1 * DIMX + c;
                a[0] += v1.x * v1.x; a[1] += v1.y * v1.y;
                a[2] += v1.z * v1.z; a[3] += v1.w * v1.w;
                if (c4 < 16) {
                    float* b = s1base + t1 * NSC + c;
                    b[0] += v1.x; b[1] += v1.y; b[2] += v1.z; b[3] += v1.w;
                }
                if (c4 == 0) scnt[rs * NT + t1] += 1.0f;
            }
        }
    }
    __syncthreads();

    // reduce RS copies, push to global with atomics
    for (int i = tid; i < NT * DIMX; i += 256) {
        float s = s2[i] + s2[NT*DIMX + i] + s2[2*NT*DIMX + i] + s2[3*NT*DIMX + i];
        atomicAdd(&g_scr[i], s);
    }
    for (int i = tid; i < NT * NSC; i += 256) {
        float s = s1[i] + s1[NT*NSC + i] + s1[2*NT*NSC + i] + s1[3*NT*NSC + i];
        atomicAdd(&g_scr[SCR_SUM1 + i], s);
    }
    if (tid < NT) {
        float s = scnt[tid] + scnt[NT + tid] + scnt[2*NT + tid] + scnt[3*NT + tid];
        atomicAdd(&g_scr[SCR_CNT + tid], s);
    }
}

// ---------------------------------------------------------------- table build
__global__ __launch_bounds__(DIMX) void k_tables(const float* __restrict__ w,
                                                 const float* __restrict__ b) {
    const int e = threadIdx.x;
    for (int t = 0; t < NT; t++) {
        float cnt = fmaxf(g_scr[SCR_CNT + t], 1.0f);
        float inv = 1.0f / cnt;
        float A, Bv;
        if (e < NSC) {
            float S2   = g_scr[t * DIMX + e];
            float S1   = g_scr[SCR_SUM1 + t * NSC + e];
            float mean = S1 * inv;
            float var  = S2 * inv - mean * mean;
            float s    = rsqrtf(var + EPSV) * w[t * NF + e];
            A  = s;
            Bv = b[t * NSC + e] - mean * s;
        } else if (e < 64 + 32 * 3) {
            int m    = (e - 64) / 3;
            int base = 64 + m * 3;
            float S2 = g_scr[t * DIMX + base] + g_scr[t * DIMX + base + 1] +
                       g_scr[t * DIMX + base + 2];
            float fn = S2 * inv * (1.0f / 3.0f);
            A  = rsqrtf(fn + EPSV) * w[t * NF + 64 + m];
            Bv = 0.0f;
        } else {
            int m    = (e - 160) / 5;
            int base = 160 + m * 5;
            float S2 = 0.0f;
#pragma unroll
            for (int j = 0; j < 5; j++) S2 += g_scr[t * DIMX + base + j];
            float fn = S2 * inv * 0.2f;
            A  = rsqrtf(fn + EPSV) * w[t * NF + 96 + m];
            Bv = 0.0f;
        }
        g_A[t * DIMX + e] = A;
        g_B[t * DIMX + e] = Bv;
    }
}

// ---------------------------------------------------------------- apply pass
// 2 float4 per thread (segments i and i+total), loads front-batched.
__global__ __launch_bounds__(256) void k_apply(const float4* __restrict__ x4,
                                               const int* __restrict__ ty,
                                               float4* __restrict__ o4,
                                               int n4, int total) {
    const unsigned i0 = blockIdx.x * 256u + threadIdx.x;
    const unsigned i1 = i0 + (unsigned)total;

    const float4* A4 = reinterpret_cast<const float4*>(g_A);
    const float4* B4 = reinterpret_cast<const float4*>(g_B);

    float4 xv0, xv1, a0, a1, b0, b1;
    bool g0 = i0 < (unsigned)n4;
    bool g1 = i1 < (unsigned)n4;
    unsigned k0 = 0, k1 = 0;

    if (g0) {
        unsigned row = i0 / 60u;
        unsigned q   = i0 - row * 60u;
        int t = __ldg(ty + row);
        k0  = t * 60u + q;
        xv0 = __ldg(x4 + i0);
    }
    if (g1) {
        unsigned row = i1 / 60u;
        unsigned q   = i1 - row * 60u;
        int t = __ldg(ty + row);
        k1  = t * 60u + q;
        xv1 = __ldg(x4 + i1);
    }
    if (g0) { a0 = A4[k0]; b0 = B4[k0]; }
    if (g1) { a1 = A4[k1]; b1 = B4[k1]; }

    if (g0) {
        float4 o;
        o.x = fmaf(xv0.x, a0.x, b0.x);
        o.y = fmaf(xv0.y, a0.y, b0.y);
        o.z = fmaf(xv0.z, a0.z, b0.z);
        o.w = fmaf(xv0.w, a0.w, b0.w);
        o4[i0] = o;
    }
    if (g1) {
        float4 o;
        o.x = fmaf(xv1.x, a1.x, b1.x);
        o.y = fmaf(xv1.y, a1.y, b1.y);
        o.z = fmaf(xv1.z, a1.z, b1.z);
        o.w = fmaf(xv1.w, a1.w, b1.w);
        o4[i1] = o;
    }
}

// ---------------------------------------------------------------- launch
extern "C" void kernel_launch(void* const* d_in, const int* in_sizes, int n_in,
                              void* d_out, int out_size) {
    const float* x  = (const float*)d_in[0];
    const int*   ty = (const int*)d_in[1];
    const float* w  = (const float*)d_in[2];
    const float* b  = (const float*)d_in[3];

    int batch = in_sizes[0] / DIMX;

    k_zero<<<(SCR_SIZE + 255) / 256, 256>>>();
    k_stats<<<592, 256>>>(x, ty, batch);
    k_tables<<<1, DIMX>>>(w, b);

    int n4    = batch * (DIMX / 4);
    int total = (n4 + 1) / 2;            // threads; each does 2 float4
    k_apply<<<(total + 255) / 256, 256>>>((const float4*)x, ty, (float4*)d_out,
                                          n4, total);
}

// round 5
// speedup vs baseline: 1.3097x; 1.1414x over previous
#include <cuda_runtime.h>

#define NT   10
#define DIMX 240
#define NSC  64
#define NF   112
#define EPSV 1e-5f
#define RS   4           // replicated accumulator copies (row-subgroups)

// scratch layout: [sum2: NT*DIMX][sum1: NT*NSC][cnt: NT]
#define SCR_SUM1 (NT*DIMX)
#define SCR_CNT  (NT*DIMX + NT*NSC)
#define SCR_SIZE (NT*DIMX + NT*NSC + NT)

__device__ float g_scr[SCR_SIZE];
__device__ __align__(16) float g_A[NT*DIMX];
__device__ __align__(16) float g_B[NT*DIMX];

// ---------------------------------------------------------------- zero scratch
__global__ void k_zero() {
    int i = blockIdx.x * blockDim.x + threadIdx.x;
    if (i < SCR_SIZE) g_scr[i] = 0.0f;
}

// packed-f32x2 shared-memory RMW: s[0..3] += v*v (acc) — one LDS.128,
// two FFMA2 on the f32x2 pipe, one STS.128.
__device__ __forceinline__ void rmw_fma2(unsigned sa, unsigned long long v01,
                                         unsigned long long v23) {
    asm volatile(
        "{\n\t"
        ".reg .b64 a0, a1;\n\t"
        "ld.shared.v2.b64 {a0, a1}, [%0];\n\t"
        "fma.rn.f32x2 a0, %1, %1, a0;\n\t"
        "fma.rn.f32x2 a1, %2, %2, a1;\n\t"
        "st.shared.v2.b64 [%0], {a0, a1};\n\t"
        "}"
        :: "r"(sa), "l"(v01), "l"(v23));
}

// packed-f32x2 shared-memory RMW: s[0..3] += v
__device__ __forceinline__ void rmw_add2(unsigned sa, unsigned long long v01,
                                         unsigned long long v23) {
    asm volatile(
        "{\n\t"
        ".reg .b64 a0, a1;\n\t"
        "ld.shared.v2.b64 {a0, a1}, [%0];\n\t"
        "add.rn.f32x2 a0, a0, %1;\n\t"
        "add.rn.f32x2 a1, a1, %2;\n\t"
        "st.shared.v2.b64 [%0], {a0, a1};\n\t"
        "}"
        :: "r"(sa), "l"(v01), "l"(v23));
}

// ---------------------------------------------------------------- stats pass
// blockDim = 256 (threads 0..239 active).
//   rs = tid/60 : accumulator copy / row-subgroup (0..3)
//   c4 = tid%60 : float4 column group
// Each CTA iteration consumes 16 rows (4 per thread, loads front-batched).
// Exclusive (rs, column) ownership -> plain vectorized smem RMW, no atomics.
__global__ __launch_bounds__(256) void k_stats(const float* __restrict__ x,
                                               const int* __restrict__ ty,
                                               int batch) {
    __shared__ __align__(16) float s2[RS * NT * DIMX];
    __shared__ __align__(16) float s1[RS * NT * NSC];
    __shared__ float scnt[RS * NT];

    const int tid = threadIdx.x;
    for (int i = tid; i < RS * NT * DIMX; i += 256) s2[i] = 0.0f;
    for (int i = tid; i < RS * NT * NSC;  i += 256) s1[i] = 0.0f;
    if (tid < RS * NT) scnt[tid] = 0.0f;
    __syncthreads();

    const int  rs  = tid / 60;
    const int  c4  = tid - rs * 60;
    const int  c   = c4 * 4;
    const bool act = (tid < 240);
    const bool sc  = act && (c4 < 16);   // scalar columns
    const bool cn  = act && (c4 == 0);   // count owner

    const unsigned sa2 = (unsigned)__cvta_generic_to_shared(s2)
                       + (rs * NT * DIMX + c) * 4u;
    const unsigned sa1 = (unsigned)__cvta_generic_to_shared(s1)
                       + (rs * NT * NSC + c) * 4u;

    const int step = gridDim.x * 16;
    for (int base = blockIdx.x * 16; base < batch; base += step) {
        if (act) {
            ulonglong2 u[4];
            int t[4];
            bool g[4];
#pragma unroll
            for (int i = 0; i < 4; i++) {
                int r = base + rs + i * 4;
                g[i] = (r < batch);
                if (g[i]) {
                    u[i] = __ldg((const ulonglong2*)(x + (size_t)r * DIMX + c));
                    t[i] = __ldg(ty + r);
                }
            }
#pragma unroll
            for (int i = 0; i < 4; i++) {
                if (g[i]) {
                    rmw_fma2(sa2 + t[i] * (DIMX * 4), u[i].x, u[i].y);
                    if (sc) rmw_add2(sa1 + t[i] * (NSC * 4), u[i].x, u[i].y);
                    if (cn) scnt[rs * NT + t[i]] += 1.0f;
                }
            }
        }
    }
    __syncthreads();

    // reduce RS copies, push to global with atomics
    for (int i = tid; i < NT * DIMX; i += 256) {
        float s = s2[i] + s2[NT*DIMX + i] + s2[2*NT*DIMX + i] + s2[3*NT*DIMX + i];
        atomicAdd(&g_scr[i], s);
    }
    for (int i = tid; i < NT * NSC; i += 256) {
        float s = s1[i] + s1[NT*NSC + i] + s1[2*NT*NSC + i] + s1[3*NT*NSC + i];
        atomicAdd(&g_scr[SCR_SUM1 + i], s);
    }
    if (tid < NT) {
        float s = scnt[tid] + scnt[NT + tid] + scnt[2*NT + tid] + scnt[3*NT + tid];
        atomicAdd(&g_scr[SCR_CNT + tid], s);
    }
}

// ---------------------------------------------------------------- table build
__global__ __launch_bounds__(DIMX) void k_tables(const float* __restrict__ w,
                                                 const float* __restrict__ b) {
    const int e = threadIdx.x;
    for (int t = 0; t < NT; t++) {
        float cnt = fmaxf(g_scr[SCR_CNT + t], 1.0f);
        float inv = 1.0f / cnt;
        float A, Bv;
        if (e < NSC) {
            float S2   = g_scr[t * DIMX + e];
            float S1   = g_scr[SCR_SUM1 + t * NSC + e];
            float mean = S1 * inv;
            float var  = S2 * inv - mean * mean;
            float s    = rsqrtf(var + EPSV) * w[t * NF + e];
            A  = s;
            Bv = b[t * NSC + e] - mean * s;
        } else if (e < 64 + 32 * 3) {
            int m    = (e - 64) / 3;
            int base = 64 + m * 3;
            float S2 = g_scr[t * DIMX + base] + g_scr[t * DIMX + base + 1] +
                       g_scr[t * DIMX + base + 2];
            float fn = S2 * inv * (1.0f / 3.0f);
            A  = rsqrtf(fn + EPSV) * w[t * NF + 64 + m];
            Bv = 0.0f;
        } else {
            int m    = (e - 160) / 5;
            int base = 160 + m * 5;
            float S2 = 0.0f;
#pragma unroll
            for (int j = 0; j < 5; j++) S2 += g_scr[t * DIMX + base + j];
            float fn = S2 * inv * 0.2f;
            A  = rsqrtf(fn + EPSV) * w[t * NF + 96 + m];
            Bv = 0.0f;
        }
        g_A[t * DIMX + e] = A;
        g_B[t * DIMX + e] = Bv;
    }
}

// ---------------------------------------------------------------- apply pass
// Reversed block order: stats streamed x ascending, so the tail of x is
// L2-resident; apply consumes it back-to-front. Each block covers one
// contiguous 512-float4 (8 KB) window: thread does i0 and i0+256.
// Output uses streaming stores to avoid evicting the x residue.
__global__ __launch_bounds__(256) void k_apply(const float4* __restrict__ x4,
                                               const int* __restrict__ ty,
                                               float4* __restrict__ o4,
                                               int n4) {
    const unsigned chunk = gridDim.x - 1u - blockIdx.x;
    const unsigned i0 = chunk * 512u + threadIdx.x;
    const unsigned i1 = i0 + 256u;

    const float4* A4 = reinterpret_cast<const float4*>(g_A);
    const float4* B4 = reinterpret_cast<const float4*>(g_B);

    float4 xv0, xv1, a0, a1, b0, b1;
    const bool g0 = i0 < (unsigned)n4;
    const bool g1 = i1 < (unsigned)n4;
    unsigned k0 = 0, k1 = 0;

    if (g0) {
        unsigned row = i0 / 60u;
        unsigned q   = i0 - row * 60u;
        int t = __ldg(ty + row);
        k0  = t * 60u + q;
        xv0 = x4[i0];
    }
    if (g1) {
        unsigned row = i1 / 60u;
        unsigned q   = i1 - row * 60u;
        int t = __ldg(ty + row);
        k1  = t * 60u + q;
        xv1 = x4[i1];
    }
    if (g0) { a0 = A4[k0]; b0 = B4[k0]; }
    if (g1) { a1 = A4[k1]; b1 = B4[k1]; }

    if (g0) {
        float4 o;
        o.x = fmaf(xv0.x, a0.x, b0.x);
        o.y = fmaf(xv0.y, a0.y, b0.y);
        o.z = fmaf(xv0.z, a0.z, b0.z);
        o.w = fmaf(xv0.w, a0.w, b0.w);
        __stcs(&o4[i0], o);
    }
    if (g1) {
        float4 o;
        o.x = fmaf(xv1.x, a1.x, b1.x);
        o.y = fmaf(xv1.y, a1.y, b1.y);
        o.z = fmaf(xv1.z, a1.z, b1.z);
        o.w = fmaf(xv1.w, a1.w, b1.w);
        __stcs(&o4[i1], o);
    }
}

// ---------------------------------------------------------------- launch
extern "C" void kernel_launch(void* const* d_in, const int* in_sizes, int n_in,
                              void* d_out, int out_size) {
    const float* x  = (const float*)d_in[0];
    const int*   ty = (const int*)d_in[1];
    const float* w  = (const float*)d_in[2];
    const float* b  = (const float*)d_in[3];

    int batch = in_sizes[0] / DIMX;

    k_zero<<<(SCR_SIZE + 255) / 256, 256>>>();
    k_stats<<<592, 256>>>(x, ty, batch);
    k_tables<<<1, DIMX>>>(w, b);

    int n4 = batch * (DIMX / 4);
    k_apply<<<(n4 + 511) / 512, 256>>>((const float4*)x, ty, (float4*)d_out, n4);
}